// round 3
// baseline (speedup 1.0000x reference)
#include <cuda_runtime.h>

#define BB 64
#define VV 2000
#define DD 16
#define CI 64
#define CO 64
#define OPAD 65

// ---------------- scratch (device globals, no allocation) ----------------
__device__ float g_partG[32 * 512];
__device__ float g_inv_norm;
__device__ float g_Zre[BB * DD * CI];
__device__ float g_Zim[BB * DD * CI];
__device__ float g_yre[(size_t)BB * VV * CI];
__device__ float g_yim[(size_t)BB * VV * CI];
__device__ float4 g_C4[(size_t)VV * CI * CO];  // (Ar, Cr, Ci, Ar+Ai)
__device__ float  g_C1[(size_t)VV * CI * CO];  // Cr+Ci

// ---------------- 1a: Gram partials  G[d,e] = sum_v conj(ne[v,d]) ne[v,e] ----------------
__global__ void gram_partial(const float* __restrict__ ner, const float* __restrict__ nei) {
    int blk = blockIdx.x;
    int v0 = blk * 63;
    int cnt = min(63, VV - v0);
    __shared__ float sr[63 * 16], si[63 * 16];
    for (int t = threadIdx.x; t < cnt * 16; t += 256) {
        sr[t] = ner[v0 * 16 + t];
        si[t] = nei[v0 * 16 + t];
    }
    __syncthreads();
    int d = threadIdx.x >> 4, e = threadIdx.x & 15;
    float ar = 0.f, ai = 0.f;
    for (int vv = 0; vv < cnt; vv++) {
        float a = sr[vv * 16 + d], b = si[vv * 16 + d];
        float c = sr[vv * 16 + e], dd = si[vv * 16 + e];
        ar += a * c + b * dd;
        ai += a * dd - b * c;
    }
    g_partG[blk * 512 + threadIdx.x * 2]     = ar;
    g_partG[blk * 512 + threadIdx.x * 2 + 1] = ai;
}

// ---------------- 1b: reduce Gram, inv_norm = rsqrt(sum |G|^2) ----------------
__global__ void gram_reduce() {
    __shared__ float red[256];
    int t = threadIdx.x;
    float gr = 0.f, gi = 0.f;
    for (int blk = 0; blk < 32; blk++) {
        gr += g_partG[blk * 512 + t * 2];
        gi += g_partG[blk * 512 + t * 2 + 1];
    }
    red[t] = gr * gr + gi * gi;
    __syncthreads();
    for (int s = 128; s > 0; s >>= 1) {
        if (t < s) red[t] += red[t + s];
        __syncthreads();
    }
    if (t == 0) g_inv_norm = rsqrtf(red[0]);
}

// ---------------- 2: Z[b,d,i] = sum_v conj(ne[v,d]) * x[b,v,i] ----------------
__global__ void __launch_bounds__(256) z_kernel(const float* __restrict__ x,
                                                const float* __restrict__ ner,
                                                const float* __restrict__ nei) {
    int b = blockIdx.y;
    int d0 = blockIdx.x * 4;
    int i = threadIdx.x & 63;
    int dl = threadIdx.x >> 6;
    __shared__ float xs[64 * 64];
    __shared__ float nr[64 * 4], ni[64 * 4];
    float ar = 0.f, ai = 0.f;
    for (int v0 = 0; v0 < VV; v0 += 64) {
        int cnt = min(64, VV - v0);
        __syncthreads();
        for (int t = threadIdx.x; t < cnt * 64; t += 256)
            xs[t] = x[(size_t)b * VV * 64 + (size_t)v0 * 64 + t];
        for (int t = threadIdx.x; t < cnt * 4; t += 256) {
            int vv = t >> 2, dd = t & 3;
            nr[t] = ner[(v0 + vv) * 16 + d0 + dd];
            ni[t] = nei[(v0 + vv) * 16 + d0 + dd];
        }
        __syncthreads();
        for (int vv = 0; vv < cnt; vv++) {
            float xv = xs[vv * 64 + i];
            ar += nr[vv * 4 + dl] * xv;
            ai -= ni[vv * 4 + dl] * xv;
        }
    }
    g_Zre[(b * 16 + d0 + dl) * 64 + i] = ar;
    g_Zim[(b * 16 + d0 + dl) * 64 + i] = ai;
}

// ---------------- 3: y[b,v,i] = sum_d ne[v,d] * Z[b,d,i] ----------------
__global__ void __launch_bounds__(256) y_kernel(const float* __restrict__ ner,
                                                const float* __restrict__ nei) {
    int b = blockIdx.y;
    int v0 = blockIdx.x * 64;
    int vcnt = min(64, VV - v0);
    __shared__ float Zr[16 * 64], Zi[16 * 64], nr[64 * 16], ni[64 * 16];
    for (int t = threadIdx.x; t < 1024; t += 256) {
        Zr[t] = g_Zre[b * 1024 + t];
        Zi[t] = g_Zim[b * 1024 + t];
    }
    for (int t = threadIdx.x; t < vcnt * 16; t += 256) {
        nr[t] = ner[v0 * 16 + t];
        ni[t] = nei[v0 * 16 + t];
    }
    __syncthreads();
    int i = threadIdx.x & 63;
    int vb = threadIdx.x >> 6;
    float zr[16], zi[16];
#pragma unroll
    for (int d = 0; d < 16; d++) { zr[d] = Zr[d * 64 + i]; zi[d] = Zi[d * 64 + i]; }
    for (int vl = vb; vl < vcnt; vl += 4) {
        float yr = 0.f, yi = 0.f;
#pragma unroll
        for (int d = 0; d < 16; d++) {
            float a = nr[vl * 16 + d], c = ni[vl * 16 + d];
            yr += a * zr[d] - c * zi[d];
            yi += a * zi[d] + c * zr[d];
        }
        size_t o = (size_t)b * VV * 64 + (size_t)(v0 + vl) * 64 + i;
        g_yre[o] = yr;
        g_yim[o] = yi;
    }
}

// ---------------- 4: combined per-node weights ----------------
__global__ void __launch_bounds__(256) wcomb_kernel(const float* __restrict__ ner,
                                                    const float* __restrict__ nei,
                                                    const float* __restrict__ wr,
                                                    const float* __restrict__ wi) {
    int io = blockIdx.x * 256 + threadIdx.x;
    int vstart = blockIdx.y * 100;
    float s = g_inv_norm;
    float P0r[16], P0i[16], P1r[16], P1i[16];
#pragma unroll
    for (int d = 0; d < 16; d++) {
        float r0 = wr[(d * 3 + 0) * 4096 + io];
        float r1 = wr[(d * 3 + 1) * 4096 + io];
        float r2 = wr[(d * 3 + 2) * 4096 + io];
        float i0 = wi[(d * 3 + 0) * 4096 + io];
        float i1 = wi[(d * 3 + 1) * 4096 + io];
        float i2 = wi[(d * 3 + 2) * 4096 + io];
        P0r[d] = r0 - r2;
        P0i[d] = i0 - i2;
        P1r[d] = (r1 + 2.f * r2) * s;
        P1i[d] = (i1 + 2.f * i2) * s;
    }
    __shared__ float nr[100 * 16], ni[100 * 16];
    for (int t = threadIdx.x; t < 100 * 16; t += 256) {
        nr[t] = ner[vstart * 16 + t];
        ni[t] = nei[vstart * 16 + t];
    }
    __syncthreads();
    for (int vl = 0; vl < 100; vl++) {
        float Ar = 0.f, Ai = 0.f, Cr = 0.f, Ci = 0.f;
#pragma unroll
        for (int d = 0; d < 16; d++) {
            float a = nr[vl * 16 + d], b = ni[vl * 16 + d];
            Ar += a * P0r[d] - b * P0i[d];
            Ai += a * P0i[d] + b * P0r[d];
            Cr += a * P1r[d] - b * P1i[d];
            Ci += a * P1i[d] + b * P1r[d];
        }
        size_t off = (size_t)(vstart + vl) * 4096 + io;
        g_C4[off] = make_float4(Ar, Cr, Ci, Ar + Ai);
        g_C1[off] = Cr + Ci;
    }
}

// ---------------- 5: final per-node GEMM (Karatsuba 5-FMA complex) ----------------
// a1 += x*Ar + yr*Cr ; a2 += yi*Ci ; a3 += x*(Ar+Ai) + (yr+yi)*(Cr+Ci)
// re = a1 - a2 ; im = a3 - a1 - a2
__global__ void __launch_bounds__(128) out3_kernel(const float* __restrict__ x,
                                                   const float* __restrict__ ner,
                                                   const float* __restrict__ nei,
                                                   const float* __restrict__ bre,
                                                   const float* __restrict__ bim,
                                                   float* __restrict__ out) {
    extern __shared__ float sm[];
    float4* sC4 = (float4*)sm;                 // [64 i][32 o] -> 8192 floats
    float*  sC1 = sm + 8192;                   // 2048
    float*  xs  = sm + 10240;                  // [i][OPAD]
    float*  yrs = xs  + 64 * OPAD;
    float*  yis = yrs + 64 * OPAD;
    float*  yss = yis + 64 * OPAD;
    float2* bs  = (float2*)(yss + 64 * OPAD);  // 32 (o-half bias)

    int oh = blockIdx.x;       // o-half
    int v  = blockIdx.y;
    int tid = threadIdx.x;

    // coefficients for this o-half
    size_t cbase = (size_t)v * 4096 + oh * 32;
    for (int n = tid; n < 2048; n += 128) {
        int i = n >> 5, o = n & 31;
        sC4[n] = g_C4[cbase + i * 64 + o];
        sC1[n] = g_C1[cbase + i * 64 + o];
    }
    // operands transposed to [i][b]
    for (int n = tid; n < 4096; n += 128) {
        int b = n >> 6, i = n & 63;
        size_t go = ((size_t)b * VV + v) * 64 + i;
        float xv = x[go];
        float yr = g_yre[go];
        float yi = g_yim[go];
        xs[i * OPAD + b]  = xv;
        yrs[i * OPAD + b] = yr;
        yis[i * OPAD + b] = yi;
        yss[i * OPAD + b] = yr + yi;
    }
    if (tid < 32) {
        int o = oh * 32 + tid;
        float r = 0.f, m = 0.f;
#pragma unroll
        for (int d = 0; d < 16; d++) {
            float a = ner[v * 16 + d], b2 = nei[v * 16 + d];
            float pr = bre[d * 64 + o], pi = bim[d * 64 + o];
            r += a * pr - b2 * pi;
            m += a * pi + b2 * pr;
        }
        bs[tid] = make_float2(r, m);
    }
    __syncthreads();

    int og = tid & 7;      // local o = og*4 .. +3
    int bg = tid >> 3;     // b = bg*4 .. +3

    float a1[4][4] = {}, a2[4][4] = {}, a3[4][4] = {};
#pragma unroll 2
    for (int i = 0; i < 64; i++) {
        float4 c4[4];
#pragma unroll
        for (int ol = 0; ol < 4; ol++) c4[ol] = sC4[i * 32 + og * 4 + ol];
        float4 c1v = *(const float4*)&sC1[i * 32 + og * 4];
        float c1[4] = {c1v.x, c1v.y, c1v.z, c1v.w};
        float xv[4], yrv[4], yiv[4], ysv[4];
        const float* xr  = xs  + i * OPAD + bg * 4;
        const float* yrr = yrs + i * OPAD + bg * 4;
        const float* yir = yis + i * OPAD + bg * 4;
        const float* ysr = yss + i * OPAD + bg * 4;
#pragma unroll
        for (int k = 0; k < 4; k++) {
            xv[k] = xr[k]; yrv[k] = yrr[k]; yiv[k] = yir[k]; ysv[k] = ysr[k];
        }
#pragma unroll
        for (int k = 0; k < 4; k++) {
#pragma unroll
            for (int ol = 0; ol < 4; ol++) {
                a1[k][ol] += xv[k] * c4[ol].x;
                a1[k][ol] += yrv[k] * c4[ol].y;
                a2[k][ol] += yiv[k] * c4[ol].z;
                a3[k][ol] += xv[k] * c4[ol].w;
                a3[k][ol] += ysv[k] * c1[ol];
            }
        }
    }

    // epilogue
#pragma unroll
    for (int k = 0; k < 4; k++) {
        int b = bg * 4 + k;
        size_t obase = ((size_t)b * VV + v) * 128 + 2 * (oh * 32 + og * 4);
        float buf[8];
#pragma unroll
        for (int ol = 0; ol < 4; ol++) {
            float2 bv = bs[og * 4 + ol];
            float re = a1[k][ol] - a2[k][ol];
            float im = a3[k][ol] - a1[k][ol] - a2[k][ol];
            buf[2 * ol]     = re + bv.x;
            buf[2 * ol + 1] = im + bv.y;
        }
        *(float4*)(out + obase)     = *(float4*)&buf[0];
        *(float4*)(out + obase + 4) = *(float4*)&buf[4];
    }
}

extern "C" void kernel_launch(void* const* d_in, const int* in_sizes, int n_in,
                              void* d_out, int out_size) {
    const float* x   = (const float*)d_in[0];
    const float* ner = (const float*)d_in[1];
    const float* nei = (const float*)d_in[2];
    const float* wr  = (const float*)d_in[3];
    const float* wi  = (const float*)d_in[4];
    const float* bre = (const float*)d_in[5];
    const float* bim = (const float*)d_in[6];
    float* out = (float*)d_out;

    int smem_out = (10240 + 4 * 64 * OPAD + 64) * 4;
    cudaFuncSetAttribute(out3_kernel, cudaFuncAttributeMaxDynamicSharedMemorySize, smem_out);

    gram_partial<<<32, 256>>>(ner, nei);
    gram_reduce<<<1, 256>>>();
    z_kernel<<<dim3(4, BB), 256>>>(x, ner, nei);
    y_kernel<<<dim3(32, BB), 256>>>(ner, nei);
    wcomb_kernel<<<dim3(16, 20), 256>>>(ner, nei, wr, wi);
    out3_kernel<<<dim3(2, VV), 128, smem_out>>>(x, ner, nei, bre, bim, out);
}

// round 4
// speedup vs baseline: 1.2597x; 1.2597x over previous
#include <cuda_runtime.h>

#define BB 64
#define VV 2000
#define DD 16
#define CI 64
#define CO 64
#define OPS 68   // operand smem row stride (floats), mult of 4 for LDS.128 alignment

// ---------------- scratch (device globals, no allocation) ----------------
__device__ float g_partG[32 * 512];
__device__ float g_inv_norm;
__device__ float g_Zre[BB * DD * CI];
__device__ float g_Zim[BB * DD * CI];
__device__ float g_yre[(size_t)BB * VV * CI];
__device__ float g_yim[(size_t)BB * VV * CI];
__device__ float4 g_AC[(size_t)VV * CI * CO];   // (Ar, Ai, Cr, Ci) per (v, i, o)

// ---------------- 1a: Gram partials  G[d,e] = sum_v conj(ne[v,d]) ne[v,e] ----------------
__global__ void gram_partial(const float* __restrict__ ner, const float* __restrict__ nei) {
    int blk = blockIdx.x;
    int v0 = blk * 63;
    int cnt = min(63, VV - v0);
    __shared__ float sr[63 * 16], si[63 * 16];
    for (int t = threadIdx.x; t < cnt * 16; t += 256) {
        sr[t] = ner[v0 * 16 + t];
        si[t] = nei[v0 * 16 + t];
    }
    __syncthreads();
    int d = threadIdx.x >> 4, e = threadIdx.x & 15;
    float ar = 0.f, ai = 0.f;
    for (int vv = 0; vv < cnt; vv++) {
        float a = sr[vv * 16 + d], b = si[vv * 16 + d];
        float c = sr[vv * 16 + e], dd = si[vv * 16 + e];
        ar += a * c + b * dd;
        ai += a * dd - b * c;
    }
    g_partG[blk * 512 + threadIdx.x * 2]     = ar;
    g_partG[blk * 512 + threadIdx.x * 2 + 1] = ai;
}

// ---------------- 1b: reduce Gram, inv_norm = rsqrt(sum |G|^2) ----------------
__global__ void gram_reduce() {
    __shared__ float red[256];
    int t = threadIdx.x;
    float gr = 0.f, gi = 0.f;
    for (int blk = 0; blk < 32; blk++) {
        gr += g_partG[blk * 512 + t * 2];
        gi += g_partG[blk * 512 + t * 2 + 1];
    }
    red[t] = gr * gr + gi * gi;
    __syncthreads();
    for (int s = 128; s > 0; s >>= 1) {
        if (t < s) red[t] += red[t + s];
        __syncthreads();
    }
    if (t == 0) g_inv_norm = rsqrtf(red[0]);
}

// ---------------- 2: Z[b,d,i] = sum_v conj(ne[v,d]) * x[b,v,i] ----------------
__global__ void __launch_bounds__(256) z_kernel(const float* __restrict__ x,
                                                const float* __restrict__ ner,
                                                const float* __restrict__ nei) {
    int b = blockIdx.y;
    int d0 = blockIdx.x * 4;
    int i = threadIdx.x & 63;
    int dl = threadIdx.x >> 6;
    __shared__ float xs[64 * 64];
    __shared__ float nr[64 * 4], ni[64 * 4];
    float ar = 0.f, ai = 0.f;
    for (int v0 = 0; v0 < VV; v0 += 64) {
        int cnt = min(64, VV - v0);
        __syncthreads();
        for (int t = threadIdx.x; t < cnt * 64; t += 256)
            xs[t] = x[(size_t)b * VV * 64 + (size_t)v0 * 64 + t];
        for (int t = threadIdx.x; t < cnt * 4; t += 256) {
            int vv = t >> 2, dd = t & 3;
            nr[t] = ner[(v0 + vv) * 16 + d0 + dd];
            ni[t] = nei[(v0 + vv) * 16 + d0 + dd];
        }
        __syncthreads();
        for (int vv = 0; vv < cnt; vv++) {
            float xv = xs[vv * 64 + i];
            ar += nr[vv * 4 + dl] * xv;
            ai -= ni[vv * 4 + dl] * xv;
        }
    }
    g_Zre[(b * 16 + d0 + dl) * 64 + i] = ar;
    g_Zim[(b * 16 + d0 + dl) * 64 + i] = ai;
}

// ---------------- 3: y[b,v,i] = sum_d ne[v,d] * Z[b,d,i] ----------------
__global__ void __launch_bounds__(256) y_kernel(const float* __restrict__ ner,
                                                const float* __restrict__ nei) {
    int b = blockIdx.y;
    int v0 = blockIdx.x * 64;
    int vcnt = min(64, VV - v0);
    __shared__ float Zr[16 * 64], Zi[16 * 64], nr[64 * 16], ni[64 * 16];
    for (int t = threadIdx.x; t < 1024; t += 256) {
        Zr[t] = g_Zre[b * 1024 + t];
        Zi[t] = g_Zim[b * 1024 + t];
    }
    for (int t = threadIdx.x; t < vcnt * 16; t += 256) {
        nr[t] = ner[v0 * 16 + t];
        ni[t] = nei[v0 * 16 + t];
    }
    __syncthreads();
    int i = threadIdx.x & 63;
    int vb = threadIdx.x >> 6;
    float zr[16], zi[16];
#pragma unroll
    for (int d = 0; d < 16; d++) { zr[d] = Zr[d * 64 + i]; zi[d] = Zi[d * 64 + i]; }
    for (int vl = vb; vl < vcnt; vl += 4) {
        float yr = 0.f, yi = 0.f;
#pragma unroll
        for (int d = 0; d < 16; d++) {
            float a = nr[vl * 16 + d], c = ni[vl * 16 + d];
            yr += a * zr[d] - c * zi[d];
            yi += a * zi[d] + c * zr[d];
        }
        size_t o = (size_t)b * VV * 64 + (size_t)(v0 + vl) * 64 + i;
        g_yre[o] = yr;
        g_yim[o] = yi;
    }
}

// ---------------- 4: combined per-node weights, interleaved float4 ----------------
__global__ void __launch_bounds__(256) wcomb_kernel(const float* __restrict__ ner,
                                                    const float* __restrict__ nei,
                                                    const float* __restrict__ wr,
                                                    const float* __restrict__ wi) {
    int io = blockIdx.x * 256 + threadIdx.x;
    int vstart = blockIdx.y * 100;
    float s = g_inv_norm;
    float P0r[16], P0i[16], P1r[16], P1i[16];
#pragma unroll
    for (int d = 0; d < 16; d++) {
        float r0 = wr[(d * 3 + 0) * 4096 + io];
        float r1 = wr[(d * 3 + 1) * 4096 + io];
        float r2 = wr[(d * 3 + 2) * 4096 + io];
        float i0 = wi[(d * 3 + 0) * 4096 + io];
        float i1 = wi[(d * 3 + 1) * 4096 + io];
        float i2 = wi[(d * 3 + 2) * 4096 + io];
        P0r[d] = r0 - r2;
        P0i[d] = i0 - i2;
        P1r[d] = (r1 + 2.f * r2) * s;
        P1i[d] = (i1 + 2.f * i2) * s;
    }
    __shared__ float nr[100 * 16], ni[100 * 16];
    for (int t = threadIdx.x; t < 100 * 16; t += 256) {
        nr[t] = ner[vstart * 16 + t];
        ni[t] = nei[vstart * 16 + t];
    }
    __syncthreads();
    for (int vl = 0; vl < 100; vl++) {
        float Ar = 0.f, Ai = 0.f, Cr = 0.f, Ci = 0.f;
#pragma unroll
        for (int d = 0; d < 16; d++) {
            float a = nr[vl * 16 + d], b = ni[vl * 16 + d];
            Ar += a * P0r[d] - b * P0i[d];
            Ai += a * P0i[d] + b * P0r[d];
            Cr += a * P1r[d] - b * P1i[d];
            Ci += a * P1i[d] + b * P1r[d];
        }
        g_AC[(size_t)(vstart + vl) * 4096 + io] = make_float4(Ar, Ai, Cr, Ci);
    }
}

// ---------------- 5: final per-node GEMM, 8b x 4o thread tiles ----------------
// re = x*Ar + yr*Cr - yi*Ci ; im = x*Ai + yr*Ci + yi*Cr
__global__ void __launch_bounds__(128) out4_kernel(const float* __restrict__ x,
                                                   const float* __restrict__ ner,
                                                   const float* __restrict__ nei,
                                                   const float* __restrict__ bre,
                                                   const float* __restrict__ bim,
                                                   float* __restrict__ out) {
    extern __shared__ float sm[];
    float4* sC  = (float4*)sm;                  // [64 i][64 o] float4 -> 16384 floats
    float*  xs  = sm + 16384;                   // [i][OPS]
    float*  yrs = xs  + 64 * OPS;
    float*  yis = yrs + 64 * OPS;
    float2* bs  = (float2*)(yis + 64 * OPS);    // 64 o

    int v  = blockIdx.x;
    int tid = threadIdx.x;

    // coefficients: 4096 float4, coalesced
    {
        const float4* g4 = g_AC + (size_t)v * 4096;
        for (int n = tid; n < 4096; n += 128) sC[n] = g4[n];
    }
    // operands transposed to [i][b]
    for (int n = tid; n < 4096; n += 128) {
        int b = n >> 6, i = n & 63;
        size_t go = ((size_t)b * VV + v) * 64 + i;
        xs[i * OPS + b]  = x[go];
        yrs[i * OPS + b] = g_yre[go];
        yis[i * OPS + b] = g_yim[go];
    }
    // bias
    if (tid < 64) {
        int o = tid;
        float r = 0.f, m = 0.f;
#pragma unroll
        for (int d = 0; d < 16; d++) {
            float a = ner[v * 16 + d], b2 = nei[v * 16 + d];
            float pr = bre[d * 64 + o], pi = bim[d * 64 + o];
            r += a * pr - b2 * pi;
            m += a * pi + b2 * pr;
        }
        bs[o] = make_float2(r, m);
    }
    __syncthreads();

    // og slow (tid>>3, 0..15): coeff loads broadcast within warp.
    // bg fast (tid&7, 0..7): b = bg*8, operand LDS.128 pairs.
    int og = tid >> 3;     // o = og*4 .. +3
    int bg = tid & 7;      // b = bg*8 .. +7

    float aR[8][4] = {}, aI[8][4] = {};

#pragma unroll 2
    for (int i = 0; i < 64; i++) {
        float4 c[4];
#pragma unroll
        for (int ol = 0; ol < 4; ol++) c[ol] = sC[i * 64 + og * 4 + ol];

        const float* xr  = xs  + i * OPS + bg * 8;
        const float* yrr = yrs + i * OPS + bg * 8;
        const float* yir = yis + i * OPS + bg * 8;
        float4 x0 = *(const float4*)(xr);
        float4 x1 = *(const float4*)(xr + 4);
        float4 r0 = *(const float4*)(yrr);
        float4 r1 = *(const float4*)(yrr + 4);
        float4 m0 = *(const float4*)(yir);
        float4 m1 = *(const float4*)(yir + 4);
        float xv[8]  = {x0.x, x0.y, x0.z, x0.w, x1.x, x1.y, x1.z, x1.w};
        float yrv[8] = {r0.x, r0.y, r0.z, r0.w, r1.x, r1.y, r1.z, r1.w};
        float yiv[8] = {m0.x, m0.y, m0.z, m0.w, m1.x, m1.y, m1.z, m1.w};

#pragma unroll
        for (int k = 0; k < 8; k++) {
#pragma unroll
            for (int ol = 0; ol < 4; ol++) {
                aR[k][ol] += xv[k]  * c[ol].x;
                aR[k][ol] += yrv[k] * c[ol].z;
                aR[k][ol] -= yiv[k] * c[ol].w;
                aI[k][ol] += xv[k]  * c[ol].y;
                aI[k][ol] += yrv[k] * c[ol].w;
                aI[k][ol] += yiv[k] * c[ol].z;
            }
        }
    }

    // epilogue: interleave (re,im), add bias, float4 stores
    float2 bv[4];
#pragma unroll
    for (int ol = 0; ol < 4; ol++) bv[ol] = bs[og * 4 + ol];
#pragma unroll
    for (int k = 0; k < 8; k++) {
        int b = bg * 8 + k;
        size_t obase = ((size_t)b * VV + v) * 128 + (size_t)(og * 8);
        float buf[8];
#pragma unroll
        for (int ol = 0; ol < 4; ol++) {
            buf[2 * ol]     = aR[k][ol] + bv[ol].x;
            buf[2 * ol + 1] = aI[k][ol] + bv[ol].y;
        }
        *(float4*)(out + obase)     = *(float4*)&buf[0];
        *(float4*)(out + obase + 4) = *(float4*)&buf[4];
    }
}

extern "C" void kernel_launch(void* const* d_in, const int* in_sizes, int n_in,
                              void* d_out, int out_size) {
    const float* x   = (const float*)d_in[0];
    const float* ner = (const float*)d_in[1];
    const float* nei = (const float*)d_in[2];
    const float* wr  = (const float*)d_in[3];
    const float* wi  = (const float*)d_in[4];
    const float* bre = (const float*)d_in[5];
    const float* bim = (const float*)d_in[6];
    float* out = (float*)d_out;

    int smem_out = (16384 + 3 * 64 * OPS + 128) * 4;
    cudaFuncSetAttribute(out4_kernel, cudaFuncAttributeMaxDynamicSharedMemorySize, smem_out);

    gram_partial<<<32, 256>>>(ner, nei);
    gram_reduce<<<1, 256>>>();
    z_kernel<<<dim3(4, BB), 256>>>(x, ner, nei);
    y_kernel<<<dim3(32, BB), 256>>>(ner, nei);
    wcomb_kernel<<<dim3(16, 20), 256>>>(ner, nei, wr, wi);
    out4_kernel<<<VV, 128, smem_out>>>(x, ner, nei, bre, bim, out);
}

// round 5
// speedup vs baseline: 1.2996x; 1.0317x over previous
#include <cuda_runtime.h>

#define BB 64
#define VV 2000
#define DD 16
#define CI 64
#define CO 64
#define OPS 68   // operand smem row stride (floats)

// ---------------- scratch (device globals, no allocation) ----------------
__device__ float g_partG[32 * 512];
__device__ float g_inv_norm;
__device__ float g_Zre[BB * DD * CI];
__device__ float g_Zim[BB * DD * CI];
__device__ float g_yre[(size_t)BB * VV * CI];
__device__ float g_yim[(size_t)BB * VV * CI];
__device__ float4 g_AC[(size_t)VV * CI * CO];   // (Ar, Ai, Cr, Ci) per (v, i, o)

// ---------------- 1a: Gram partials  G[d,e] = sum_v conj(ne[v,d]) ne[v,e] ----------------
__global__ void gram_partial(const float* __restrict__ ner, const float* __restrict__ nei) {
    int blk = blockIdx.x;
    int v0 = blk * 63;
    int cnt = min(63, VV - v0);
    __shared__ float sr[63 * 16], si[63 * 16];
    for (int t = threadIdx.x; t < cnt * 16; t += 256) {
        sr[t] = ner[v0 * 16 + t];
        si[t] = nei[v0 * 16 + t];
    }
    __syncthreads();
    int d = threadIdx.x >> 4, e = threadIdx.x & 15;
    float ar = 0.f, ai = 0.f;
    for (int vv = 0; vv < cnt; vv++) {
        float a = sr[vv * 16 + d], b = si[vv * 16 + d];
        float c = sr[vv * 16 + e], dd = si[vv * 16 + e];
        ar += a * c + b * dd;
        ai += a * dd - b * c;
    }
    g_partG[blk * 512 + threadIdx.x * 2]     = ar;
    g_partG[blk * 512 + threadIdx.x * 2 + 1] = ai;
}

// ---------------- 1b: reduce Gram, inv_norm = rsqrt(sum |G|^2) ----------------
__global__ void gram_reduce() {
    __shared__ float red[256];
    int t = threadIdx.x;
    float gr = 0.f, gi = 0.f;
    for (int blk = 0; blk < 32; blk++) {
        gr += g_partG[blk * 512 + t * 2];
        gi += g_partG[blk * 512 + t * 2 + 1];
    }
    red[t] = gr * gr + gi * gi;
    __syncthreads();
    for (int s = 128; s > 0; s >>= 1) {
        if (t < s) red[t] += red[t + s];
        __syncthreads();
    }
    if (t == 0) g_inv_norm = rsqrtf(red[0]);
}

// ---------------- 2: Z[b,d,i] = sum_v conj(ne[v,d]) * x[b,v,i] ----------------
__global__ void __launch_bounds__(256) z_kernel(const float* __restrict__ x,
                                                const float* __restrict__ ner,
                                                const float* __restrict__ nei) {
    int b = blockIdx.y;
    int d0 = blockIdx.x * 4;
    int i = threadIdx.x & 63;
    int dl = threadIdx.x >> 6;
    __shared__ float xs[64 * 64];
    __shared__ float nr[64 * 4], ni[64 * 4];
    float ar = 0.f, ai = 0.f;
    for (int v0 = 0; v0 < VV; v0 += 64) {
        int cnt = min(64, VV - v0);
        __syncthreads();
        for (int t = threadIdx.x; t < cnt * 64; t += 256)
            xs[t] = x[(size_t)b * VV * 64 + (size_t)v0 * 64 + t];
        for (int t = threadIdx.x; t < cnt * 4; t += 256) {
            int vv = t >> 2, dd = t & 3;
            nr[t] = ner[(v0 + vv) * 16 + d0 + dd];
            ni[t] = nei[(v0 + vv) * 16 + d0 + dd];
        }
        __syncthreads();
        for (int vv = 0; vv < cnt; vv++) {
            float xv = xs[vv * 64 + i];
            ar += nr[vv * 4 + dl] * xv;
            ai -= ni[vv * 4 + dl] * xv;
        }
    }
    g_Zre[(b * 16 + d0 + dl) * 64 + i] = ar;
    g_Zim[(b * 16 + d0 + dl) * 64 + i] = ai;
}

// ---------------- 3: y[b,v,i] = sum_d ne[v,d] * Z[b,d,i] ----------------
__global__ void __launch_bounds__(256) y_kernel(const float* __restrict__ ner,
                                                const float* __restrict__ nei) {
    int b = blockIdx.y;
    int v0 = blockIdx.x * 64;
    int vcnt = min(64, VV - v0);
    __shared__ float Zr[16 * 64], Zi[16 * 64], nr[64 * 16], ni[64 * 16];
    for (int t = threadIdx.x; t < 1024; t += 256) {
        Zr[t] = g_Zre[b * 1024 + t];
        Zi[t] = g_Zim[b * 1024 + t];
    }
    for (int t = threadIdx.x; t < vcnt * 16; t += 256) {
        nr[t] = ner[v0 * 16 + t];
        ni[t] = nei[v0 * 16 + t];
    }
    __syncthreads();
    int i = threadIdx.x & 63;
    int vb = threadIdx.x >> 6;
    float zr[16], zi[16];
#pragma unroll
    for (int d = 0; d < 16; d++) { zr[d] = Zr[d * 64 + i]; zi[d] = Zi[d * 64 + i]; }
    for (int vl = vb; vl < vcnt; vl += 4) {
        float yr = 0.f, yi = 0.f;
#pragma unroll
        for (int d = 0; d < 16; d++) {
            float a = nr[vl * 16 + d], c = ni[vl * 16 + d];
            yr += a * zr[d] - c * zi[d];
            yi += a * zi[d] + c * zr[d];
        }
        size_t o = (size_t)b * VV * 64 + (size_t)(v0 + vl) * 64 + i;
        g_yre[o] = yr;
        g_yim[o] = yi;
    }
}

// ---------------- 4: combined per-node weights, interleaved float4 ----------------
__global__ void __launch_bounds__(256) wcomb_kernel(const float* __restrict__ ner,
                                                    const float* __restrict__ nei,
                                                    const float* __restrict__ wr,
                                                    const float* __restrict__ wi) {
    int io = blockIdx.x * 256 + threadIdx.x;
    int vstart = blockIdx.y * 100;
    float s = g_inv_norm;
    float P0r[16], P0i[16], P1r[16], P1i[16];
#pragma unroll
    for (int d = 0; d < 16; d++) {
        float r0 = wr[(d * 3 + 0) * 4096 + io];
        float r1 = wr[(d * 3 + 1) * 4096 + io];
        float r2 = wr[(d * 3 + 2) * 4096 + io];
        float i0 = wi[(d * 3 + 0) * 4096 + io];
        float i1 = wi[(d * 3 + 1) * 4096 + io];
        float i2 = wi[(d * 3 + 2) * 4096 + io];
        P0r[d] = r0 - r2;
        P0i[d] = i0 - i2;
        P1r[d] = (r1 + 2.f * r2) * s;
        P1i[d] = (i1 + 2.f * i2) * s;
    }
    __shared__ float nr[100 * 16], ni[100 * 16];
    for (int t = threadIdx.x; t < 100 * 16; t += 256) {
        nr[t] = ner[vstart * 16 + t];
        ni[t] = nei[vstart * 16 + t];
    }
    __syncthreads();
    for (int vl = 0; vl < 100; vl++) {
        float Ar = 0.f, Ai = 0.f, Cr = 0.f, Ci = 0.f;
#pragma unroll
        for (int d = 0; d < 16; d++) {
            float a = nr[vl * 16 + d], b = ni[vl * 16 + d];
            Ar += a * P0r[d] - b * P0i[d];
            Ai += a * P0i[d] + b * P0r[d];
            Cr += a * P1r[d] - b * P1i[d];
            Ci += a * P1i[d] + b * P1r[d];
        }
        g_AC[(size_t)(vstart + vl) * 4096 + io] = make_float4(Ar, Ai, Cr, Ci);
    }
}

// ---------------- 5: final GEMM, o-half blocks, 256 thr, 2 blocks/SM ----------------
// re = x*Ar + yr*Cr - yi*Ci ; im = x*Ai + yr*Ci + yi*Cr
__global__ void __launch_bounds__(256) out5_kernel(const float* __restrict__ x,
                                                   const float* __restrict__ ner,
                                                   const float* __restrict__ nei,
                                                   const float* __restrict__ bre,
                                                   const float* __restrict__ bim,
                                                   float* __restrict__ out) {
    extern __shared__ float sm[];
    float4* sC  = (float4*)sm;                  // [64 i][32 o] float4 -> 8192 floats
    float*  xs  = sm + 8192;                    // [i][OPS]
    float*  yrs = xs  + 64 * OPS;
    float*  yis = yrs + 64 * OPS;
    float2* bs  = (float2*)(yis + 64 * OPS);    // 32 o

    int oh = blockIdx.x;       // o-half: 0/1
    int v  = blockIdx.y;
    int tid = threadIdx.x;

    // coefficients for this o-half: 2048 float4
    {
        const float4* g4 = g_AC + (size_t)v * 4096 + oh * 32;
        for (int n = tid; n < 2048; n += 256) {
            int i = n >> 5, o = n & 31;
            sC[n] = g4[i * 64 + o];
        }
    }
    // operands transposed to [i][b]
    for (int n = tid; n < 4096; n += 256) {
        int b = n >> 6, i = n & 63;
        size_t go = ((size_t)b * VV + v) * 64 + i;
        xs[i * OPS + b]  = x[go];
        yrs[i * OPS + b] = g_yre[go];
        yis[i * OPS + b] = g_yim[go];
    }
    // bias for this o-half
    if (tid < 32) {
        int o = oh * 32 + tid;
        float r = 0.f, m = 0.f;
#pragma unroll
        for (int d = 0; d < 16; d++) {
            float a = ner[v * 16 + d], b2 = nei[v * 16 + d];
            float pr = bre[d * 64 + o], pi = bim[d * 64 + o];
            r += a * pr - b2 * pi;
            m += a * pi + b2 * pr;
        }
        bs[tid] = make_float2(r, m);
    }
    __syncthreads();

    // og slow (tid>>4, 0..15): 2 o each, coeff LDS broadcast (2 addrs/warp).
    // bg fast (tid&15, 0..15): 4 b each, contiguous LDS.128.
    int og = tid >> 4;
    int bg = tid & 15;

    float aR[4][2] = {}, aI[4][2] = {};

#pragma unroll 4
    for (int i = 0; i < 64; i++) {
        float4 c0 = sC[i * 32 + og * 2];
        float4 c1 = sC[i * 32 + og * 2 + 1];

        const float* xr  = xs  + i * OPS + bg * 4;
        const float* yrr = yrs + i * OPS + bg * 4;
        const float* yir = yis + i * OPS + bg * 4;
        float4 xq = *(const float4*)xr;
        float4 rq = *(const float4*)yrr;
        float4 mq = *(const float4*)yir;
        float xv[4]  = {xq.x, xq.y, xq.z, xq.w};
        float yrv[4] = {rq.x, rq.y, rq.z, rq.w};
        float yiv[4] = {mq.x, mq.y, mq.z, mq.w};

#pragma unroll
        for (int k = 0; k < 4; k++) {
            aR[k][0] += xv[k]  * c0.x;
            aR[k][0] += yrv[k] * c0.z;
            aR[k][0] -= yiv[k] * c0.w;
            aI[k][0] += xv[k]  * c0.y;
            aI[k][0] += yrv[k] * c0.w;
            aI[k][0] += yiv[k] * c0.z;
            aR[k][1] += xv[k]  * c1.x;
            aR[k][1] += yrv[k] * c1.z;
            aR[k][1] -= yiv[k] * c1.w;
            aI[k][1] += xv[k]  * c1.y;
            aI[k][1] += yrv[k] * c1.w;
            aI[k][1] += yiv[k] * c1.z;
        }
    }

    // epilogue: (re,im) interleaved for 2 consecutive o -> one float4 per b
    float2 b0 = bs[og * 2], b1 = bs[og * 2 + 1];
#pragma unroll
    for (int k = 0; k < 4; k++) {
        int b = bg * 4 + k;
        size_t obase = ((size_t)b * VV + v) * 128 + (size_t)(oh * 64 + og * 4);
        *(float4*)(out + obase) = make_float4(aR[k][0] + b0.x, aI[k][0] + b0.y,
                                              aR[k][1] + b1.x, aI[k][1] + b1.y);
    }
}

extern "C" void kernel_launch(void* const* d_in, const int* in_sizes, int n_in,
                              void* d_out, int out_size) {
    const float* x   = (const float*)d_in[0];
    const float* ner = (const float*)d_in[1];
    const float* nei = (const float*)d_in[2];
    const float* wr  = (const float*)d_in[3];
    const float* wi  = (const float*)d_in[4];
    const float* bre = (const float*)d_in[5];
    const float* bim = (const float*)d_in[6];
    float* out = (float*)d_out;

    int smem_out = (8192 + 3 * 64 * OPS + 64) * 4;   // ~84 KB -> 2 blocks/SM
    cudaFuncSetAttribute(out5_kernel, cudaFuncAttributeMaxDynamicSharedMemorySize, smem_out);

    gram_partial<<<32, 256>>>(ner, nei);
    gram_reduce<<<1, 256>>>();
    z_kernel<<<dim3(4, BB), 256>>>(x, ner, nei);
    y_kernel<<<dim3(32, BB), 256>>>(ner, nei);
    wcomb_kernel<<<dim3(16, 20), 256>>>(ner, nei, wr, wi);
    out5_kernel<<<dim3(2, VV), 256, smem_out>>>(x, ner, nei, bre, bim, out);
}

// round 6
// speedup vs baseline: 1.5596x; 1.2001x over previous
#include <cuda_runtime.h>

#define BB 64
#define VV 2000
#define DD 16
#define CI 64
#define CO 64

// ---------------- scratch (device globals, no allocation) ----------------
__device__ float g_partG[32 * 512];
__device__ float g_inv_norm;
__device__ float g_Zre[BB * DD * CI];
__device__ float g_Zim[BB * DD * CI];
__device__ float g_yre[(size_t)BB * VV * CI];
__device__ float g_yim[(size_t)BB * VV * CI];
__device__ float g_Are[(size_t)VV * CI * CO];
__device__ float g_Aim[(size_t)VV * CI * CO];
__device__ float g_Cre[(size_t)VV * CI * CO];
__device__ float g_Cim[(size_t)VV * CI * CO];

// ================ K1: gram_partial (blocks 0-31)  +  z (blocks 32-287) ================
__global__ void __launch_bounds__(256) k1_gram_z(const float* __restrict__ x,
                                                 const float* __restrict__ ner,
                                                 const float* __restrict__ nei) {
    __shared__ float sm[4608];
    if (blockIdx.x < 32) {
        // ---- gram_partial: G[d,e] partial over 63 v ----
        float* sr = sm;            // 1008
        float* si = sm + 1008;     // 1008
        int blk = blockIdx.x;
        int v0 = blk * 63;
        int cnt = min(63, VV - v0);
        for (int t = threadIdx.x; t < cnt * 16; t += 256) {
            sr[t] = ner[v0 * 16 + t];
            si[t] = nei[v0 * 16 + t];
        }
        __syncthreads();
        int d = threadIdx.x >> 4, e = threadIdx.x & 15;
        float ar = 0.f, ai = 0.f;
        for (int vv = 0; vv < cnt; vv++) {
            float a = sr[vv * 16 + d], b = si[vv * 16 + d];
            float c = sr[vv * 16 + e], dd = si[vv * 16 + e];
            ar += a * c + b * dd;
            ai += a * dd - b * c;
        }
        g_partG[blk * 512 + threadIdx.x * 2]     = ar;
        g_partG[blk * 512 + threadIdx.x * 2 + 1] = ai;
    } else {
        // ---- z: Z[b,d,i] = sum_v conj(ne[v,d]) * x[b,v,i] ----
        float* xs = sm;            // 4096
        float* nr = sm + 4096;     // 256
        float* ni = sm + 4352;     // 256
        int bx = blockIdx.x - 32;
        int b = bx >> 2;
        int d0 = (bx & 3) * 4;
        int i = threadIdx.x & 63;
        int dl = threadIdx.x >> 6;
        float ar = 0.f, ai = 0.f;
        for (int v0 = 0; v0 < VV; v0 += 64) {
            int cnt = min(64, VV - v0);
            __syncthreads();
            for (int t = threadIdx.x; t < cnt * 64; t += 256)
                xs[t] = x[(size_t)b * VV * 64 + (size_t)v0 * 64 + t];
            for (int t = threadIdx.x; t < cnt * 4; t += 256) {
                int vv = t >> 2, dd = t & 3;
                nr[t] = ner[(v0 + vv) * 16 + d0 + dd];
                ni[t] = nei[(v0 + vv) * 16 + d0 + dd];
            }
            __syncthreads();
            for (int vv = 0; vv < cnt; vv++) {
                float xv = xs[vv * 64 + i];
                ar += nr[vv * 4 + dl] * xv;
                ai -= ni[vv * 4 + dl] * xv;
            }
        }
        g_Zre[(b * 16 + d0 + dl) * 64 + i] = ar;
        g_Zim[(b * 16 + d0 + dl) * 64 + i] = ai;
    }
}

// ================ K2: gram_reduce (block 0)  +  y (blocks 1-2048) ================
__global__ void __launch_bounds__(256) k2_reduce_y(const float* __restrict__ ner,
                                                   const float* __restrict__ nei) {
    __shared__ float sm[4096];
    if (blockIdx.x == 0) {
        // ---- gram reduce -> inv_norm ----
        float* red = sm;
        int t = threadIdx.x;
        float gr = 0.f, gi = 0.f;
        for (int blk = 0; blk < 32; blk++) {
            gr += g_partG[blk * 512 + t * 2];
            gi += g_partG[blk * 512 + t * 2 + 1];
        }
        red[t] = gr * gr + gi * gi;
        __syncthreads();
        for (int s = 128; s > 0; s >>= 1) {
            if (t < s) red[t] += red[t + s];
            __syncthreads();
        }
        if (t == 0) g_inv_norm = rsqrtf(red[0]);
    } else {
        // ---- y[b,v,i] = sum_d ne[v,d] * Z[b,d,i] ----
        float* Zr = sm;            // 1024
        float* Zi = sm + 1024;     // 1024
        float* nr = sm + 2048;     // 1024
        float* ni = sm + 3072;     // 1024
        int bx = blockIdx.x - 1;
        int b = bx >> 5;
        int v0 = (bx & 31) * 64;
        int vcnt = min(64, VV - v0);
        for (int t = threadIdx.x; t < 1024; t += 256) {
            Zr[t] = g_Zre[b * 1024 + t];
            Zi[t] = g_Zim[b * 1024 + t];
        }
        for (int t = threadIdx.x; t < vcnt * 16; t += 256) {
            nr[t] = ner[v0 * 16 + t];
            ni[t] = nei[v0 * 16 + t];
        }
        __syncthreads();
        int i = threadIdx.x & 63;
        int vb = threadIdx.x >> 6;
        float zr[16], zi[16];
#pragma unroll
        for (int d = 0; d < 16; d++) { zr[d] = Zr[d * 64 + i]; zi[d] = Zi[d * 64 + i]; }
        for (int vl = vb; vl < vcnt; vl += 4) {
            float yr = 0.f, yi = 0.f;
#pragma unroll
            for (int d = 0; d < 16; d++) {
                float a = nr[vl * 16 + d], c = ni[vl * 16 + d];
                yr += a * zr[d] - c * zi[d];
                yi += a * zi[d] + c * zr[d];
            }
            size_t o = (size_t)b * VV * 64 + (size_t)(v0 + vl) * 64 + i;
            g_yre[o] = yr;
            g_yim[o] = yi;
        }
    }
}

// ================ K3: combined per-node weights (R1 layout: separate arrays) ================
__global__ void __launch_bounds__(256) wcomb_kernel(const float* __restrict__ ner,
                                                    const float* __restrict__ nei,
                                                    const float* __restrict__ wr,
                                                    const float* __restrict__ wi) {
    int io = blockIdx.x * 256 + threadIdx.x;
    int vstart = blockIdx.y * 100;
    float s = g_inv_norm;
    float P0r[16], P0i[16], P1r[16], P1i[16];
#pragma unroll
    for (int d = 0; d < 16; d++) {
        float r0 = wr[(d * 3 + 0) * 4096 + io];
        float r1 = wr[(d * 3 + 1) * 4096 + io];
        float r2 = wr[(d * 3 + 2) * 4096 + io];
        float i0 = wi[(d * 3 + 0) * 4096 + io];
        float i1 = wi[(d * 3 + 1) * 4096 + io];
        float i2 = wi[(d * 3 + 2) * 4096 + io];
        P0r[d] = r0 - r2;
        P0i[d] = i0 - i2;
        P1r[d] = (r1 + 2.f * r2) * s;
        P1i[d] = (i1 + 2.f * i2) * s;
    }
    __shared__ float nr[100 * 16], ni[100 * 16];
    for (int t = threadIdx.x; t < 100 * 16; t += 256) {
        nr[t] = ner[vstart * 16 + t];
        ni[t] = nei[vstart * 16 + t];
    }
    __syncthreads();
    for (int vl = 0; vl < 100; vl++) {
        float Ar = 0.f, Ai = 0.f, Cr = 0.f, Ci = 0.f;
#pragma unroll
        for (int d = 0; d < 16; d++) {
            float a = nr[vl * 16 + d], b = ni[vl * 16 + d];
            Ar += a * P0r[d] - b * P0i[d];
            Ai += a * P0i[d] + b * P0r[d];
            Cr += a * P1r[d] - b * P1i[d];
            Ci += a * P1i[d] + b * P1r[d];
        }
        size_t off = (size_t)(vstart + vl) * 4096 + io;
        g_Are[off] = Ar;
        g_Aim[off] = Ai;
        g_Cre[off] = Cr;
        g_Cim[off] = Ci;
    }
}

// ================ K4: final per-node GEMM (R1 body, verbatim) ================
__global__ void __launch_bounds__(256) out_kernel(const float* __restrict__ x,
                                                  const float* __restrict__ ner,
                                                  const float* __restrict__ nei,
                                                  const float* __restrict__ bre,
                                                  const float* __restrict__ bim,
                                                  float* __restrict__ out) {
    extern __shared__ float sm[];
    float* Ar = sm;            // 4096
    float* Ai = sm + 4096;
    float* Cr = sm + 8192;
    float* Ci = sm + 12288;
    float* xs = sm + 16384;    // 4096 : [b][i]
    float* yr = sm + 20480;
    float* yi = sm + 24576;
    float* br = sm + 28672;    // 64
    float* bi = sm + 28736;

    int v = blockIdx.x;
    size_t vo = (size_t)v * 4096;
    for (int t = threadIdx.x; t < 4096; t += 256) {
        Ar[t] = g_Are[vo + t];
        Ai[t] = g_Aim[vo + t];
        Cr[t] = g_Cre[vo + t];
        Ci[t] = g_Cim[vo + t];
        int b = t >> 6, i = t & 63;
        size_t xoff = (size_t)b * (VV * 64) + (size_t)v * 64 + i;
        xs[t] = x[xoff];
        yr[t] = g_yre[xoff];
        yi[t] = g_yim[xoff];
    }
    if (threadIdx.x < 64) {
        int o = threadIdx.x;
        float r = 0.f, m = 0.f;
#pragma unroll
        for (int d = 0; d < 16; d++) {
            float a = ner[v * 16 + d], b2 = nei[v * 16 + d];
            float pr = bre[d * 64 + o], pi = bim[d * 64 + o];
            r += a * pr - b2 * pi;
            m += a * pi + b2 * pr;
        }
        br[o] = r;
        bi[o] = m;
    }
    __syncthreads();

    int og = (threadIdx.x & 15) * 4;
    int bg = (threadIdx.x >> 4) * 4;
    float accR[4][4] = {}, accI[4][4] = {};
#pragma unroll 4
    for (int i = 0; i < 64; i++) {
        float xv[4], yrv[4], yiv[4];
#pragma unroll
        for (int b = 0; b < 4; b++) {
            int base = (bg + b) * 64 + i;
            xv[b] = xs[base];
            yrv[b] = yr[base];
            yiv[b] = yi[base];
        }
        float4 a4 = *(const float4*)&Ar[i * 64 + og];
        float4 b4 = *(const float4*)&Ai[i * 64 + og];
        float4 c4 = *(const float4*)&Cr[i * 64 + og];
        float4 d4 = *(const float4*)&Ci[i * 64 + og];
        float ar_[4] = {a4.x, a4.y, a4.z, a4.w};
        float ai_[4] = {b4.x, b4.y, b4.z, b4.w};
        float cr_[4] = {c4.x, c4.y, c4.z, c4.w};
        float ci_[4] = {d4.x, d4.y, d4.z, d4.w};
#pragma unroll
        for (int b = 0; b < 4; b++) {
#pragma unroll
            for (int oo = 0; oo < 4; oo++) {
                accR[b][oo] += xv[b] * ar_[oo] + yrv[b] * cr_[oo] - yiv[b] * ci_[oo];
                accI[b][oo] += xv[b] * ai_[oo] + yrv[b] * ci_[oo] + yiv[b] * cr_[oo];
            }
        }
    }
#pragma unroll
    for (int b = 0; b < 4; b++) {
        int bidx = bg + b;
        size_t ob = ((size_t)bidx * VV + v) * 128 + 2 * og;
        float buf[8];
#pragma unroll
        for (int oo = 0; oo < 4; oo++) {
            buf[2 * oo]     = accR[b][oo] + br[og + oo];
            buf[2 * oo + 1] = accI[b][oo] + bi[og + oo];
        }
        *(float4*)&out[ob]     = *(float4*)&buf[0];
        *(float4*)&out[ob + 4] = *(float4*)&buf[4];
    }
}

extern "C" void kernel_launch(void* const* d_in, const int* in_sizes, int n_in,
                              void* d_out, int out_size) {
    const float* x   = (const float*)d_in[0];
    const float* ner = (const float*)d_in[1];
    const float* nei = (const float*)d_in[2];
    const float* wr  = (const float*)d_in[3];
    const float* wi  = (const float*)d_in[4];
    const float* bre = (const float*)d_in[5];
    const float* bim = (const float*)d_in[6];
    float* out = (float*)d_out;

    cudaFuncSetAttribute(out_kernel, cudaFuncAttributeMaxDynamicSharedMemorySize, 28800 * 4);

    k1_gram_z<<<32 + BB * 4, 256>>>(x, ner, nei);          // launch 1
    k2_reduce_y<<<1 + BB * 32, 256>>>(ner, nei);           // launch 2
    wcomb_kernel<<<dim3(16, 20), 256>>>(ner, nei, wr, wi); // launch 3
    out_kernel<<<VV, 256, 28800 * 4>>>(x, ner, nei, bre, bim, out);  // launch 4 (ncu target)
}